// round 16
// baseline (speedup 1.0000x reference)
#include <cuda_runtime.h>
#include <cuda_bf16.h>
#include <math.h>

#define B   32
#define NF  16
#define HW  192
#define D   256
#define S   21
#define NA  20
#define RTOT (B*NF*HW)
#define MS   (B*S)
#define RANKS 4

__device__ __nv_bfloat16 g_Ah[RTOT*D], g_Al[RTOT*D];
__device__ float g_k[RTOT*D];
__device__ float g_v[RTOT*D];
__device__ __nv_bfloat16 g_Wkh[D*D],  g_Wkl[D*D];
__device__ __nv_bfloat16 g_Wvh[D*D],  g_Wvl[D*D];
__device__ __nv_bfloat16 g_Wqh[D*D],  g_Wql[D*D];
__device__ __nv_bfloat16 g_W1h[D*D],  g_W1l[D*D];
__device__ __nv_bfloat16 g_W2h[D*D],  g_W2l[D*D];
__device__ __nv_bfloat16 g_Wihh[3*D*D], g_Wihl[3*D*D];
__device__ __nv_bfloat16 g_Whhh[3*D*D], g_Whhl[3*D*D];
__device__ float g_slots[MS*D];
__device__ float g_q[MS*D];
__device__ float g_attn[B*S*HW];
__device__ float g_upd[MS*D];
__device__ float g_h[MS*D];
__device__ float g_t[MS*D];

#define CLUSTER_SYNC() do { \
    __syncthreads(); \
    asm volatile("barrier.cluster.arrive.aligned;" ::: "memory"); \
    asm volatile("barrier.cluster.wait.aligned;"   ::: "memory"); \
} while (0)

__device__ __forceinline__ void bsplit(float x, __nv_bfloat16& h, __nv_bfloat16& l)
{
    h = __float2bfloat16(x);
    l = __float2bfloat16(x - __bfloat162float(h));
}
__device__ __forceinline__ void mma_bf16(float* d, const unsigned* a, const unsigned* b)
{
    asm volatile(
        "mma.sync.aligned.m16n8k16.row.col.f32.bf16.bf16.f32 "
        "{%0,%1,%2,%3}, {%4,%5,%6,%7}, {%8,%9}, {%0,%1,%2,%3};\n"
        : "+f"(d[0]), "+f"(d[1]), "+f"(d[2]), "+f"(d[3])
        : "r"(a[0]), "r"(a[1]), "r"(a[2]), "r"(a[3]), "r"(b[0]), "r"(b[1]));
}
__device__ __forceinline__ void cp16(unsigned dst, const void* src)
{
    asm volatile("cp.async.cg.shared.global [%0], [%1], 16;\n" :: "r"(dst), "l"(src));
}
__device__ __forceinline__ void cp8(unsigned dst, const void* src)
{
    asm volatile("cp.async.ca.shared.global [%0], [%1], 8;\n" :: "r"(dst), "l"(src));
}
#define CP_COMMIT() asm volatile("cp.async.commit_group;\n")
#define CP_WAIT1()  asm volatile("cp.async.wait_group 1;\n" ::: "memory")
#define CP_WAIT0()  asm volatile("cp.async.wait_group 0;\n" ::: "memory")

// smem layout (bytes):
// [0,25344)          A hi/lo 24x264 bf16  (alias sQ 21x257 f32, sAtt 21x192 f32)
// [25344,92928)      resident Wq hi/lo 64x264
// [92928,203520)     stream: 2 chunk slots 55296B each / W1,W2 one-shot / v tile
// [203520,222720)    sOut 24x200 f32
#define AST 264
#define A_LO (24*264)
#define RQOFF 25344
#define STROFF 92928
#define OOFF 203520
#define OST 200
#define ONE_LO (64*264)
#define CWST 72
#define SLOT_BYTES 55296
#define VST 68
#define LOOP_SMEM 222720

__device__ __forceinline__ void ln_to_Abf(const float* __restrict__ src,
    const float* __restrict__ gam, const float* __restrict__ bet,
    __nv_bfloat16* Ah, int w, int lane)
{
    __nv_bfloat16* Al = Ah + A_LO;
    __syncthreads();
    #pragma unroll
    for (int i = 0; i < 3; i++) {
        int r = w + 8*i;
        if (r < S) {
            float x[8]; float s = 0.f;
            #pragma unroll
            for (int c = 0; c < 8; c++) { x[c] = src[(size_t)r*256 + lane + 32*c]; s += x[c]; }
            #pragma unroll
            for (int o = 16; o; o >>= 1) s += __shfl_xor_sync(~0u, s, o);
            float mean = s * (1.f/256.f);
            float vs = 0.f;
            #pragma unroll
            for (int c = 0; c < 8; c++) { float d = x[c] - mean; vs += d*d; }
            #pragma unroll
            for (int o = 16; o; o >>= 1) vs += __shfl_xor_sync(~0u, vs, o);
            float inv = rsqrtf(vs * (1.f/256.f) + 1e-5f);
            #pragma unroll
            for (int c = 0; c < 8; c++) {
                int col = lane + 32*c;
                float y = (x[c]-mean)*inv*gam[col] + bet[col];
                __nv_bfloat16 h, l; bsplit(y, h, l);
                Ah[r*AST + col] = h; Al[r*AST + col] = l;
            }
        } else {
            #pragma unroll
            for (int c = 0; c < 8; c++) {
                int col = lane + 32*c;
                Ah[r*AST + col] = __float2bfloat16(0.f);
                Al[r*AST + col] = __float2bfloat16(0.f);
            }
        }
    }
    __syncthreads();
}

__device__ __forceinline__ void copy_to_Abf(const float* __restrict__ src,
    __nv_bfloat16* Ah, int w, int lane)
{
    __nv_bfloat16* Al = Ah + A_LO;
    __syncthreads();
    #pragma unroll
    for (int i = 0; i < 3; i++) {
        int r = w + 8*i;
        #pragma unroll
        for (int c = 0; c < 8; c++) {
            int col = lane + 32*c;
            float y = (r < S) ? src[(size_t)r*256 + col] : 0.f;
            __nv_bfloat16 h, l; bsplit(y, h, l);
            Ah[r*AST + col] = h; Al[r*AST + col] = l;
        }
    }
    __syncthreads();
}

__device__ __forceinline__ void issue_full64(const __nv_bfloat16* __restrict__ Wh_g,
    const __nv_bfloat16* __restrict__ Wl_g, int rowbase, unsigned dstbase, int tid)
{
    #pragma unroll
    for (int l = 0; l < 16; l++) {
        int e = tid + l*256;
        int arr = e >> 11, x = e & 2047;
        int n = x >> 5, q = x & 31;
        const __nv_bfloat16* src = (arr ? Wl_g : Wh_g) + (size_t)(rowbase + n)*256 + q*8;
        cp16(dstbase + (unsigned)(arr*ONE_LO + n*AST + q*8)*2, src);
    }
    CP_COMMIT();
}

__device__ __forceinline__ void issue_w192(const __nv_bfloat16* __restrict__ Wh_g,
    const __nv_bfloat16* __restrict__ Wl_g, const int* colb, int kt,
    unsigned dstbase, int tid)
{
    #pragma unroll
    for (int l = 0; l < 24; l++) {
        int e = tid + l*256;
        int arr = (e >= 3072) ? 1 : 0;
        int x = e - arr*3072;
        int n = x >> 4, q = x & 15;
        const __nv_bfloat16* src =
            (arr ? Wl_g : Wh_g) + (size_t)(colb[n>>6] + (n&63))*256 + kt + q*4;
        cp8(dstbase + (unsigned)(arr*(192*CWST) + n*CWST + q*4)*2, src);
    }
    CP_COMMIT();
}

__device__ __forceinline__ void issue_v(int b, int f, int colq, unsigned dstbase, int tid)
{
    #pragma unroll
    for (int l = 0; l < 12; l++) {
        int e = tid + l*256;
        int n = e >> 4, q = e & 15;
        const float* src = g_v + ((size_t)(b*NF + f)*HW + n)*256 + colq + q*4;
        cp16(dstbase + (unsigned)(n*VST + q*4)*4, src);
    }
    CP_COMMIT();
}

// 24x64 = A[24x256] @ W^T (W fully staged, stride AST)
__device__ __forceinline__ void mma_n64(const __nv_bfloat16* Ah,
    const __nv_bfloat16* Wp, float (&acc)[2][4], int w, int lane)
{
    const __nv_bfloat16* Alp = Ah + A_LO;
    const __nv_bfloat16* Wlp = Wp + ONE_LO;
    int mt = w >> 2, nq = w & 3;
    int r = lane >> 2, c = lane & 3;
    int arow = mt*16 + r;
    #pragma unroll
    for (int g = 0; g < 2; g++)
        #pragma unroll
        for (int j = 0; j < 4; j++) acc[g][j] = 0.f;
    #pragma unroll
    for (int k16 = 0; k16 < 16; k16++) {
        int k0 = k16*16;
        unsigned ah[4], al[4];
        const __nv_bfloat16* p = Ah + arow*AST + k0 + 2*c;
        ah[0] = *(const unsigned*)p;
        ah[1] = *(const unsigned*)(p + 8*AST);
        ah[2] = *(const unsigned*)(p + 8);
        ah[3] = *(const unsigned*)(p + 8*AST + 8);
        const __nv_bfloat16* q = Alp + arow*AST + k0 + 2*c;
        al[0] = *(const unsigned*)q;
        al[1] = *(const unsigned*)(q + 8*AST);
        al[2] = *(const unsigned*)(q + 8);
        al[3] = *(const unsigned*)(q + 8*AST + 8);
        #pragma unroll
        for (int g = 0; g < 2; g++) {
            int n = (nq*2 + g)*8 + r;
            const __nv_bfloat16* ph = Wp + n*AST + k0 + 2*c;
            unsigned bh[2] = { *(const unsigned*)ph, *(const unsigned*)(ph + 8) };
            const __nv_bfloat16* pl = Wlp + n*AST + k0 + 2*c;
            unsigned bl[2] = { *(const unsigned*)pl, *(const unsigned*)(pl + 8) };
            mma_bf16(acc[g], ah, bh);
            mma_bf16(acc[g], ah, bl);
            mma_bf16(acc[g], al, bh);
        }
    }
}

// 24x192 chunked gemm, 4 chunks of 64k, double-buffered, chunk0 pre-issued to slot1
__device__ __forceinline__ void gemm_n192(const __nv_bfloat16* __restrict__ Wh_g,
    const __nv_bfloat16* __restrict__ Wl_g, const int* colb,
    const __nv_bfloat16* Ah, char* sm, unsigned strbase, float* sOut,
    int tid, int w, int lane)
{
    const __nv_bfloat16* Alp = Ah + A_LO;
    float acc[6][4];
    #pragma unroll
    for (int g = 0; g < 6; g++)
        #pragma unroll
        for (int j = 0; j < 4; j++) acc[g][j] = 0.f;
    int mt = w >> 2, nq = w & 3;
    int r = lane >> 2, c = lane & 3;
    int arow = mt*16 + r;

    #pragma unroll
    for (int ch = 0; ch < 4; ch++) {
        if (ch < 3) {
            int slot = ((ch+1) & 1) ^ 1;
            issue_w192(Wh_g, Wl_g, colb, (ch+1)*64, strbase + slot*SLOT_BYTES, tid);
            CP_WAIT1();
        } else {
            CP_WAIT0();
        }
        __syncthreads();
        const __nv_bfloat16* Wh_s =
            (const __nv_bfloat16*)(sm + STROFF + ((ch & 1) ^ 1)*SLOT_BYTES);
        const __nv_bfloat16* Wl_s = Wh_s + 192*CWST;
        #pragma unroll
        for (int k16 = 0; k16 < 4; k16++) {
            int k0 = ch*64 + k16*16, kw = k16*16;
            unsigned ah[4], al[4];
            const __nv_bfloat16* p = Ah + arow*AST + k0 + 2*c;
            ah[0] = *(const unsigned*)p;
            ah[1] = *(const unsigned*)(p + 8*AST);
            ah[2] = *(const unsigned*)(p + 8);
            ah[3] = *(const unsigned*)(p + 8*AST + 8);
            const __nv_bfloat16* q = Alp + arow*AST + k0 + 2*c;
            al[0] = *(const unsigned*)q;
            al[1] = *(const unsigned*)(q + 8*AST);
            al[2] = *(const unsigned*)(q + 8);
            al[3] = *(const unsigned*)(q + 8*AST + 8);
            #pragma unroll
            for (int g = 0; g < 6; g++) {
                int n = (nq*6 + g)*8 + r;
                const __nv_bfloat16* ph = Wh_s + n*CWST + kw + 2*c;
                unsigned bh[2] = { *(const unsigned*)ph, *(const unsigned*)(ph + 8) };
                const __nv_bfloat16* pl = Wl_s + n*CWST + kw + 2*c;
                unsigned bl[2] = { *(const unsigned*)pl, *(const unsigned*)(pl + 8) };
                mma_bf16(acc[g], ah, bh);
                mma_bf16(acc[g], ah, bl);
                mma_bf16(acc[g], al, bh);
            }
        }
        if (ch < 3) __syncthreads();
    }
    #pragma unroll
    for (int g = 0; g < 6; g++) {
        int row0 = mt*16 + r;
        int cc = (nq*6 + g)*8 + 2*c;
        sOut[row0*OST + cc]     = acc[g][0];
        sOut[row0*OST + cc + 1] = acc[g][1];
        if (mt == 0) {
            sOut[(row0+8)*OST + cc]     = acc[g][2];
            sOut[(row0+8)*OST + cc + 1] = acc[g][3];
        }
    }
    __syncthreads();
}

__global__ void __cluster_dims__(RANKS, 1, 1) __launch_bounds__(256, 1)
slot_loop(
    const float* __restrict__ noise, const float* __restrict__ mu,
    const float* __restrict__ sg,
    const float* __restrict__ bq,  const float* __restrict__ b1,
    const float* __restrict__ b2,
    const float* __restrict__ bih, const float* __restrict__ bhh,
    const float* __restrict__ gsl, const float* __restrict__ besl,
    const float* __restrict__ gff, const float* __restrict__ beff,
    float* __restrict__ out, float* __restrict__ out_attn)
{
    extern __shared__ char sm[];
    __nv_bfloat16* Ah  = (__nv_bfloat16*)sm;
    float* sQ   = (float*)sm;
    float* sAtt = (float*)sm;
    __nv_bfloat16* sRq = (__nv_bfloat16*)(sm + RQOFF);
    float* sV   = (float*)(sm + STROFF);
    float* sOut = (float*)(sm + OOFF);
    unsigned strbase = (unsigned)__cvta_generic_to_shared(sm + STROFF);
    unsigned rqbase  = (unsigned)__cvta_generic_to_shared(sm + RQOFF);

    int tid  = threadIdx.x;
    int w    = tid >> 5, lane = tid & 31;
    int rank = blockIdx.x;
    int b    = blockIdx.y;
    int colq = 64*rank;
    int mt = w >> 2, nq = w & 3;
    int fr = lane >> 2, fc = lane & 3;
    int colb3[3] = { colq, 256 + colq, 512 + colq };

    float* slots_b = g_slots + (size_t)b*S*256;
    float* q_b     = g_q     + (size_t)b*S*256;
    float* upd_b   = g_upd   + (size_t)b*S*256;
    float* h_b     = g_h     + (size_t)b*S*256;
    float* t_b     = g_t     + (size_t)b*S*256;
    float* attn_b  = g_attn  + (size_t)b*S*HW;

    issue_full64(g_Wqh, g_Wql, colq, rqbase, tid);
    CP_WAIT0();
    __syncthreads();
    issue_w192(g_Whhh, g_Whhl, colb3, 0, strbase + SLOT_BYTES, tid);

    #pragma unroll
    for (int i = 0; i < 3; i++) {
        int r = w + 8*i;
        if (r < S)
            #pragma unroll
            for (int cc = 0; cc < 2; cc++) {
                int colg = colq + cc*32 + lane;
                slots_b[(size_t)r*256 + colg] =
                    mu[colg] + sg[colg]*noise[(size_t)(b*S + r)*256 + colg];
            }
    }
    CLUSTER_SYNC();

    float ghreg[3][3][2];

    for (int f = 0; f < NF; f++) {
        for (int it = 0; it < 3; it++) {
            // S1: q = LN_sl(slots)@Wq^T + bq (resident); gh = slots@Whh^T (chunked)
            ln_to_Abf(slots_b, gsl, besl, Ah, w, lane);
            {
                float acc[2][4];
                mma_n64(Ah, sRq, acc, w, lane);
                #pragma unroll
                for (int g = 0; g < 2; g++) {
                    int colg = colq + (nq*2 + g)*8 + 2*fc;
                    int row0 = mt*16 + fr;
                    if (mt == 0) {
                        q_b[(size_t)row0*256 + colg]     = acc[g][0] + bq[colg];
                        q_b[(size_t)row0*256 + colg+1]   = acc[g][1] + bq[colg+1];
                        q_b[(size_t)(row0+8)*256 + colg]   = acc[g][2] + bq[colg];
                        q_b[(size_t)(row0+8)*256 + colg+1] = acc[g][3] + bq[colg+1];
                    } else if (row0 < S) {
                        q_b[(size_t)row0*256 + colg]   = acc[g][0] + bq[colg];
                        q_b[(size_t)row0*256 + colg+1] = acc[g][1] + bq[colg+1];
                    }
                }
            }
            copy_to_Abf(slots_b, Ah, w, lane);
            gemm_n192(g_Whhh, g_Whhl, colb3, Ah, sm, strbase, sOut, tid, w, lane);
            #pragma unroll
            for (int i = 0; i < 3; i++) {
                int r = w + 8*i;
                #pragma unroll
                for (int g = 0; g < 3; g++)
                    #pragma unroll
                    for (int cc = 0; cc < 2; cc++)
                        ghreg[i][g][cc] = (r < S) ? sOut[r*OST + g*64 + cc*32 + lane] : 0.f;
            }
            CLUSTER_SYNC();

            // S2: prefetch v; dots+softmax over slot axis (48 j per rank)
            issue_v(b, f, colq, strbase, tid);
            #pragma unroll
            for (int i = 0; i < 3; i++) {
                int r = w + 8*i;
                if (r < S)
                    #pragma unroll
                    for (int c = 0; c < 8; c++)
                        sQ[r*257 + lane + 32*c] = q_b[(size_t)r*256 + lane + 32*c];
            }
            __syncthreads();
            #pragma unroll
            for (int jj = 0; jj < 6; jj++) {
                int j = 48*rank + w*6 + jj;
                const float* kr = g_k + ((size_t)(b*NF + f)*HW + j)*256;
                float kv[8];
                #pragma unroll
                for (int c = 0; c < 8; c++) kv[c] = kr[lane + 32*c];
                float myd = 0.f;
                #pragma unroll
                for (int i = 0; i < S; i++) {
                    float p = 0.f;
                    #pragma unroll
                    for (int c = 0; c < 8; c++)
                        p = fmaf(sQ[i*257 + lane + 32*c], kv[c], p);
                    #pragma unroll
                    for (int o = 16; o; o >>= 1) p += __shfl_xor_sync(~0u, p, o);
                    if (lane == i) myd = p;
                }
                float x = (lane < S) ? myd * 0.0625f : -1e30f;
                float mx = x;
                #pragma unroll
                for (int o = 16; o; o >>= 1) mx = fmaxf(mx, __shfl_xor_sync(~0u, mx, o));
                float e = (lane < S) ? expf(x - mx) : 0.f;
                float sum = e;
                #pragma unroll
                for (int o = 16; o; o >>= 1) sum += __shfl_xor_sync(~0u, sum, o);
                float a = e / sum + 1e-8f;
                if (lane < S) {
                    attn_b[(size_t)lane*HW + j] = a;
                    if (it == 2)
                        out_attn[(size_t)((b*NF + f)*S + lane)*HW + j] = a;
                }
            }
            CLUSTER_SYNC();

            // S3: prefetch Wih c0; updates = (attn/rowsum) @ v
            issue_w192(g_Wihh, g_Wihl, colb3, 0, strbase + SLOT_BYTES, tid);
            CP_WAIT1();
            __syncthreads();
            for (int l = 0; l < 16; l++) {
                int e = tid + l*256;
                if (e < S*HW) sAtt[e] = attn_b[e];
            }
            __syncthreads();
            {
                float rsv[3];
                #pragma unroll
                for (int i = 0; i < 3; i++) {
                    int r = w + 8*i;
                    if (r < S) {
                        float s = 0.f;
                        #pragma unroll
                        for (int c = 0; c < 6; c++) s += sAtt[r*HW + lane + 32*c];
                        #pragma unroll
                        for (int o = 16; o; o >>= 1) s += __shfl_xor_sync(~0u, s, o);
                        rsv[i] = s;
                    }
                }
                float ua[3][2];
                #pragma unroll
                for (int i = 0; i < 3; i++) { ua[i][0] = 0.f; ua[i][1] = 0.f; }
                int r0 = w, r1 = w + 8, r2 = w + 16;
                #pragma unroll 4
                for (int j = 0; j < HW; j++) {
                    float v0 = sV[j*VST + lane];
                    float v1 = sV[j*VST + 32 + lane];
                    float a0 = sAtt[r0*HW + j];
                    float a1 = sAtt[r1*HW + j];
                    ua[0][0] = fmaf(a0, v0, ua[0][0]); ua[0][1] = fmaf(a0, v1, ua[0][1]);
                    ua[1][0] = fmaf(a1, v0, ua[1][0]); ua[1][1] = fmaf(a1, v1, ua[1][1]);
                    if (r2 < S) {
                        float a2 = sAtt[r2*HW + j];
                        ua[2][0] = fmaf(a2, v0, ua[2][0]); ua[2][1] = fmaf(a2, v1, ua[2][1]);
                    }
                }
                #pragma unroll
                for (int i = 0; i < 3; i++) {
                    int r = w + 8*i;
                    if (r < S) {
                        upd_b[(size_t)r*256 + colq + lane]      = ua[i][0] / rsv[i];
                        upd_b[(size_t)r*256 + colq + 32 + lane] = ua[i][1] / rsv[i];
                    }
                }
            }
            CLUSTER_SYNC();

            // S4: gi gemm (c0 prefetched) + GRU -> h ; prefetch W1
            copy_to_Abf(upd_b, Ah, w, lane);
            gemm_n192(g_Wihh, g_Wihl, colb3, Ah, sm, strbase, sOut, tid, w, lane);
            issue_full64(g_W1h, g_W1l, colq, strbase, tid);
            #pragma unroll
            for (int i = 0; i < 3; i++) {
                int r = w + 8*i;
                if (r < S)
                    #pragma unroll
                    for (int cc = 0; cc < 2; cc++) {
                        int colg = colq + cc*32 + lane;
                        float irv = sOut[r*OST + cc*32 + lane]       + bih[colg];
                        float izv = sOut[r*OST + 64 + cc*32 + lane]  + bih[256 + colg];
                        float inn = sOut[r*OST + 128 + cc*32 + lane] + bih[512 + colg];
                        float hrv = ghreg[i][0][cc] + bhh[colg];
                        float hzv = ghreg[i][1][cc] + bhh[256 + colg];
                        float hnv = ghreg[i][2][cc] + bhh[512 + colg];
                        float rr = 1.f / (1.f + expf(-(irv + hrv)));
                        float zz = 1.f / (1.f + expf(-(izv + hzv)));
                        float nn = tanhf(inn + rr*hnv);
                        float sl = slots_b[(size_t)r*256 + colg];
                        h_b[(size_t)r*256 + colg] = (1.f - zz)*nn + zz*sl;
                    }
            }
            CLUSTER_SYNC();

            // S5: t = relu(LN_ff(h)@W1^T + b1) ; prefetch W2
            ln_to_Abf(h_b, gff, beff, Ah, w, lane);
            CP_WAIT0();
            __syncthreads();
            {
                float acc[2][4];
                mma_n64(Ah, (const __nv_bfloat16*)(sm + STROFF), acc, w, lane);
                #pragma unroll
                for (int g = 0; g < 2; g++) {
                    int colg = colq + (nq*2 + g)*8 + 2*fc;
                    int row0 = mt*16 + fr;
                    if (mt == 0) {
                        t_b[(size_t)row0*256 + colg]   = fmaxf(acc[g][0] + b1[colg], 0.f);
                        t_b[(size_t)row0*256 + colg+1] = fmaxf(acc[g][1] + b1[colg+1], 0.f);
                        t_b[(size_t)(row0+8)*256 + colg]   = fmaxf(acc[g][2] + b1[colg], 0.f);
                        t_b[(size_t)(row0+8)*256 + colg+1] = fmaxf(acc[g][3] + b1[colg+1], 0.f);
                    } else if (row0 < S) {
                        t_b[(size_t)row0*256 + colg]   = fmaxf(acc[g][0] + b1[colg], 0.f);
                        t_b[(size_t)row0*256 + colg+1] = fmaxf(acc[g][1] + b1[colg+1], 0.f);
                    }
                }
            }
            __syncthreads();
            issue_full64(g_W2h, g_W2l, colq, strbase, tid);
            CLUSTER_SYNC();

            // S6: slots = t@W2^T + b2 + h ; prefetch Whh c0 (next iter)
            copy_to_Abf(t_b, Ah, w, lane);
            CP_WAIT0();
            __syncthreads();
            {
                float acc[2][4];
                mma_n64(Ah, (const __nv_bfloat16*)(sm + STROFF), acc, w, lane);
                #pragma unroll
                for (int g = 0; g < 2; g++) {
                    int colg = colq + (nq*2 + g)*8 + 2*fc;
                    int row0 = mt*16 + fr;
                    if (mt == 0) {
                        slots_b[(size_t)row0*256 + colg] =
                            acc[g][0] + b2[colg]   + h_b[(size_t)row0*256 + colg];
                        slots_b[(size_t)row0*256 + colg+1] =
                            acc[g][1] + b2[colg+1] + h_b[(size_t)row0*256 + colg+1];
                        slots_b[(size_t)(row0+8)*256 + colg] =
                            acc[g][2] + b2[colg]   + h_b[(size_t)(row0+8)*256 + colg];
                        slots_b[(size_t)(row0+8)*256 + colg+1] =
                            acc[g][3] + b2[colg+1] + h_b[(size_t)(row0+8)*256 + colg+1];
                    } else if (row0 < S) {
                        slots_b[(size_t)row0*256 + colg] =
                            acc[g][0] + b2[colg]   + h_b[(size_t)row0*256 + colg];
                        slots_b[(size_t)row0*256 + colg+1] =
                            acc[g][1] + b2[colg+1] + h_b[(size_t)row0*256 + colg+1];
                    }
                }
            }
            __syncthreads();
            issue_w192(g_Whhh, g_Whhl, colb3, 0, strbase + SLOT_BYTES, tid);
            CLUSTER_SYNC();
        }
    }

    CP_WAIT0();
    #pragma unroll
    for (int i = 0; i < 3; i++) {
        int r = w + 8*i;
        if (r < NA)
            #pragma unroll
            for (int cc = 0; cc < 2; cc++) {
                int colg = colq + cc*32 + lane;
                out[(size_t)(b*NA + r)*256 + colg] = slots_b[(size_t)r*256 + colg];
            }
    }
}

// ---------------- prepass: fused k+v GEMM (unchanged from R9) ----------------
#define KVA 5120
#define KVB 20480
__global__ void __launch_bounds__(256) kv_gemm(
    const float* __restrict__ bk, float* __restrict__ Ck,
    const float* __restrict__ bv, float* __restrict__ Cv)
{
    extern __shared__ __nv_bfloat16 smkv[];
    unsigned sbase = (unsigned)__cvta_generic_to_shared(smkv);
    int m0 = blockIdx.y * 128;
    int which = blockIdx.x >> 1;
    int n0 = (blockIdx.x & 1) * 128;
    const __nv_bfloat16* Wh_g = which ? g_Wvh : g_Wkh;
    const __nv_bfloat16* Wl_g = which ? g_Wvl : g_Wkl;
    const float* bias = which ? bv : bk;
    float* C          = which ? Cv : Ck;

    int tid = threadIdx.x;
    int w = tid >> 5, lane = tid & 31;
    int wm = w >> 1, wn = w & 1;
    int r = lane >> 2, c = lane & 3;

    float acc[2][8][4];
    #pragma unroll
    for (int mt = 0; mt < 2; mt++)
        #pragma unroll
        for (int nt = 0; nt < 8; nt++)
            #pragma unroll
            for (int j = 0; j < 4; j++) acc[mt][nt][j] = 0.f;

    auto issue = [&](int kt, int buf) {
        #pragma unroll
        for (int l = 0; l < 8; l++) {
            int e = tid + l*256;
            int arr = e >> 9, x = e & 511;
            int row = x >> 2, q = x & 3;
            const __nv_bfloat16* src;
            switch (arr) {
                case 0: src = g_Ah + (size_t)(m0 + row)*256 + kt + q*8; break;
                case 1: src = g_Al + (size_t)(m0 + row)*256 + kt + q*8; break;
                case 2: src = Wh_g + (size_t)(n0 + row)*256 + kt + q*8; break;
                default:src = Wl_g + (size_t)(n0 + row)*256 + kt + q*8; break;
            }
            cp16(sbase + (unsigned)(buf*KVB + arr*KVA + row*40 + q*8)*2, src);
        }
        CP_COMMIT();
    };

    issue(0, 0);
    #pragma unroll
    for (int c8 = 0; c8 < 8; c8++) {
        if (c8 < 7) { issue((c8+1)*32, (c8+1)&1); CP_WAIT1(); }
        else        { CP_WAIT0(); }
        __syncthreads();
        const __nv_bfloat16* sAh = smkv + (c8&1)*KVB;
        const __nv_bfloat16* sAl = sAh + KVA;
        const __nv_bfloat16* sWh = sAh + 2*KVA;
        const __nv_bfloat16* sWl = sAh + 3*KVA;
        #pragma unroll
        for (int ks = 0; ks < 2; ks++) {
            int k0 = ks*16;
            unsigned ah[2][4], al[2][4];
            #pragma unroll
            for (int mt = 0; mt < 2; mt++) {
                int row = wm*32 + mt*16 + r;
                const __nv_bfloat16* p = sAh + row*40 + k0 + 2*c;
                ah[mt][0] = *(const unsigned*)p;
                ah[mt][1] = *(const unsigned*)(p + 8*40);
                ah[mt][2] = *(const unsigned*)(p + 8);
                ah[mt][3] = *(const unsigned*)(p + 8*40 + 8);
                const __nv_bfloat16* q = sAl + row*40 + k0 + 2*c;
                al[mt][0] = *(const unsigned*)q;
                al[mt][1] = *(const unsigned*)(q + 8*40);
                al[mt][2] = *(const unsigned*)(q + 8);
                al[mt][3] = *(const unsigned*)(q + 8*40 + 8);
            }
            #pragma unroll
            for (int nt = 0; nt < 8; nt++) {
                int n = wn*64 + nt*8 + r;
                const __nv_bfloat16* ph = sWh + n*40 + k0 + 2*c;
                unsigned bh[2] = { *(const unsigned*)ph, *(const unsigned*)(ph + 8) };
                const __nv_bfloat16* pl = sWl + n*40 + k0 + 2*c;
                unsigned bl[2] = { *(const unsigned*)pl, *(const unsigned*)(pl + 8) };
                #pragma unroll
                for (int mt = 0; mt < 2; mt++) {
                    mma_bf16(acc[mt][nt], ah[mt], bh);
                    mma_bf16(acc[mt][nt], ah[mt], bl);
                    mma_bf16(acc[mt][nt], al[mt], bh);
                }
            }
        }
        __syncthreads();
    }
    #pragma unroll
    for (int mt = 0; mt < 2; mt++)
        #pragma unroll
        for (int nt = 0; nt < 8; nt++) {
            int row = m0 + wm*32 + mt*16 + r;
            int cc = n0 + wn*64 + nt*8 + 2*c;
            float b0 = bias[cc], b1 = bias[cc+1];
            C[(size_t)row*256 + cc]       = acc[mt][nt][0] + b0;
            C[(size_t)row*256 + cc + 1]   = acc[mt][nt][1] + b1;
            C[(size_t)(row+8)*256 + cc]   = acc[mt][nt][2] + b0;
            C[(size_t)(row+8)*256 + cc+1] = acc[mt][nt][3] + b1;
        }
}

__global__ void __launch_bounds__(256) ln_kernel(const float* __restrict__ X,
    const float* __restrict__ g, const float* __restrict__ be)
{
    int w = threadIdx.x >> 5, lane = threadIdx.x & 31;
    size_t row = (size_t)blockIdx.x*8 + w;
    const float* Xr = X + row*256;
    float x[8]; float s = 0.f;
    #pragma unroll
    for (int c = 0; c < 8; c++) { x[c] = Xr[lane + 32*c]; s += x[c]; }
    #pragma unroll
    for (int o = 16; o; o >>= 1) s += __shfl_xor_sync(~0u, s, o);
    float mean = s * (1.f/256.f);
    float vs = 0.f;
    #pragma unroll
    for (int c = 0; c < 8; c++) { float d = x[c] - mean; vs += d*d; }
    #pragma unroll
    for (int o = 16; o; o >>= 1) vs += __shfl_xor_sync(~0u, vs, o);
    float inv = rsqrtf(vs * (1.f/256.f) + 1e-5f);
    #pragma unroll
    for (int c = 0; c < 8; c++) {
        int col = lane + 32*c;
        float y = (x[c]-mean)*inv*g[col] + be[col];
        __nv_bfloat16 h, l; bsplit(y, h, l);
        g_Ah[row*256 + col] = h;
        g_Al[row*256 + col] = l;
    }
}

__global__ void conv_split(const float* __restrict__ W,
    __nv_bfloat16* __restrict__ Hp, __nv_bfloat16* __restrict__ Lp, int n)
{
    int i = blockIdx.x*256 + threadIdx.x;
    if (i < n) {
        __nv_bfloat16 h, l; bsplit(W[i], h, l);
        Hp[i] = h; Lp[i] = l;
    }
}

extern "C" void kernel_launch(void* const* d_in, const int* in_sizes, int n_in,
                              void* d_out, int out_size)
{
    const float* inputs = (const float*)d_in[0];
    const float* noise  = (const float*)d_in[1];
    const float* mu     = (const float*)d_in[2];
    const float* sigma  = (const float*)d_in[3];
    const float* Wq  = (const float*)d_in[4];  const float* bq  = (const float*)d_in[5];
    const float* Wk  = (const float*)d_in[6];  const float* bk  = (const float*)d_in[7];
    const float* Wv  = (const float*)d_in[8];  const float* bv  = (const float*)d_in[9];
    const float* W1  = (const float*)d_in[10]; const float* b1  = (const float*)d_in[11];
    const float* W2  = (const float*)d_in[12]; const float* b2  = (const float*)d_in[13];
    const float* Wih = (const float*)d_in[14]; const float* bih = (const float*)d_in[15];
    const float* Whh = (const float*)d_in[16]; const float* bhh = (const float*)d_in[17];
    const float* gin = (const float*)d_in[18]; const float* bein = (const float*)d_in[19];
    const float* gsl = (const float*)d_in[20]; const float* besl = (const float*)d_in[21];
    const float* gff = (const float*)d_in[22]; const float* beff = (const float*)d_in[23];

    float* out = (float*)d_out;
    float* out_attn = out + (size_t)B*NA*D;

    float *kbuf, *vbuf;
    cudaGetSymbolAddress((void**)&kbuf, g_k);
    cudaGetSymbolAddress((void**)&vbuf, g_v);
    __nv_bfloat16 *wkh,*wkl,*wvh,*wvl,*wqh,*wql,*w1h,*w1l,*w2h,*w2l,*wihh,*wihl,*whhh,*whhl;
    cudaGetSymbolAddress((void**)&wkh, g_Wkh);  cudaGetSymbolAddress((void**)&wkl, g_Wkl);
    cudaGetSymbolAddress((void**)&wvh, g_Wvh);  cudaGetSymbolAddress((void**)&wvl, g_Wvl);
    cudaGetSymbolAddress((void**)&wqh, g_Wqh);  cudaGetSymbolAddress((void**)&wql, g_Wql);
    cudaGetSymbolAddress((void**)&w1h, g_W1h);  cudaGetSymbolAddress((void**)&w1l, g_W1l);
    cudaGetSymbolAddress((void**)&w2h, g_W2h);  cudaGetSymbolAddress((void**)&w2l, g_W2l);
    cudaGetSymbolAddress((void**)&wihh, g_Wihh); cudaGetSymbolAddress((void**)&wihl, g_Wihl);
    cudaGetSymbolAddress((void**)&whhh, g_Whhh); cudaGetSymbolAddress((void**)&whhl, g_Whhl);

    cudaFuncSetAttribute(slot_loop, cudaFuncAttributeMaxDynamicSharedMemorySize, LOOP_SMEM);
    cudaFuncSetAttribute(kv_gemm,   cudaFuncAttributeMaxDynamicSharedMemorySize, 2*KVB*2);

    conv_split<<<256, 256>>>(Wk,  wkh,  wkl,  D*D);
    conv_split<<<256, 256>>>(Wv,  wvh,  wvl,  D*D);
    conv_split<<<256, 256>>>(Wq,  wqh,  wql,  D*D);
    conv_split<<<256, 256>>>(W1,  w1h,  w1l,  D*D);
    conv_split<<<256, 256>>>(W2,  w2h,  w2l,  D*D);
    conv_split<<<768, 256>>>(Wih, wihh, wihl, 3*D*D);
    conv_split<<<768, 256>>>(Whh, whhh, whhl, 3*D*D);

    ln_kernel<<<RTOT/8, 256>>>(inputs, gin, bein);
    kv_gemm<<<dim3(4, RTOT/128), 256, 2*KVB*2>>>(bk, kbuf, bv, vbuf);

    slot_loop<<<dim3(RANKS, B), 256, LOOP_SMEM>>>(
        noise, mu, sigma, bq, b1, b2, bih, bhh,
        gsl, besl, gff, beff, out, out_attn);
}

// round 17
// speedup vs baseline: 1.5455x; 1.5455x over previous
#include <cuda_runtime.h>
#include <cuda_bf16.h>
#include <math.h>

#define B   32
#define NF  16
#define HW  192
#define D   256
#define S   21
#define NA  20
#define RTOT (B*NF*HW)
#define MS   (B*S)
#define RANKS 8

__device__ __nv_bfloat16 g_Ah[RTOT*D], g_Al[RTOT*D];
__device__ __nv_bfloat16 g_kh[RTOT*D], g_kl[RTOT*D];        // split k, [row][col]
__device__ __nv_bfloat16 g_vth[RTOT*D], g_vtl[RTOT*D];      // split v, [bf][col][j]
__device__ __nv_bfloat16 g_Wkh[D*D],  g_Wkl[D*D];
__device__ __nv_bfloat16 g_Wvh[D*D],  g_Wvl[D*D];
__device__ __nv_bfloat16 g_Wqh[D*D],  g_Wql[D*D];
__device__ __nv_bfloat16 g_W1h[D*D],  g_W1l[D*D];
__device__ __nv_bfloat16 g_W2h[D*D],  g_W2l[D*D];
__device__ __nv_bfloat16 g_Wihh[3*D*D], g_Wihl[3*D*D];
__device__ __nv_bfloat16 g_Whhh[3*D*D], g_Whhl[3*D*D];
__device__ float g_slots[MS*D];
__device__ float g_q[MS*D];
__device__ float g_attn[B*S*HW];
__device__ float g_upd[MS*D];
__device__ float g_h[MS*D];
__device__ float g_t[MS*D];

#define CLUSTER_SYNC() do { \
    __syncthreads(); \
    asm volatile("barrier.cluster.arrive.aligned;" ::: "memory"); \
    asm volatile("barrier.cluster.wait.aligned;"   ::: "memory"); \
} while (0)

__device__ __forceinline__ void bsplit(float x, __nv_bfloat16& h, __nv_bfloat16& l)
{
    h = __float2bfloat16(x);
    l = __float2bfloat16(x - __bfloat162float(h));
}
__device__ __forceinline__ void mma_bf16(float* d, const unsigned* a, const unsigned* b)
{
    asm volatile(
        "mma.sync.aligned.m16n8k16.row.col.f32.bf16.bf16.f32 "
        "{%0,%1,%2,%3}, {%4,%5,%6,%7}, {%8,%9}, {%0,%1,%2,%3};\n"
        : "+f"(d[0]), "+f"(d[1]), "+f"(d[2]), "+f"(d[3])
        : "r"(a[0]), "r"(a[1]), "r"(a[2]), "r"(a[3]), "r"(b[0]), "r"(b[1]));
}
__device__ __forceinline__ void cp16(unsigned dst, const void* src)
{
    asm volatile("cp.async.cg.shared.global [%0], [%1], 16;\n" :: "r"(dst), "l"(src));
}
#define CP_COMMIT() asm volatile("cp.async.commit_group;\n")
#define CP_WAIT1()  asm volatile("cp.async.wait_group 1;\n" ::: "memory")
#define CP_WAIT0()  asm volatile("cp.async.wait_group 0;\n" ::: "memory")

// smem layout (bytes):
// [0,25344)      A hi/lo 24x264 bf16
// [25344,56064)  W stream double buffer (2 x 7680 elems), also k chunks
// [56064,81664)  v_t tile 2 x 6400 elems (hi/lo, 32 x 200)
// [81664,98176)  f32 region: sOut 24x97 | sDot 24x25 | sAtt 21x192
#define AST 264
#define A_LO (24*264)
#define WOFF 25344
#define VOFF 56064
#define DOFF 81664
#define OST 97
#define LOOP_SMEM 98176
#define WST 40

__device__ __forceinline__ void ln_to_Abf(const float* __restrict__ src,
    const float* __restrict__ gam, const float* __restrict__ bet,
    __nv_bfloat16* Ah, int w, int lane)
{
    __nv_bfloat16* Al = Ah + A_LO;
    __syncthreads();
    #pragma unroll
    for (int i = 0; i < 3; i++) {
        int r = w + 8*i;
        if (r < S) {
            float x[8]; float s = 0.f;
            #pragma unroll
            for (int c = 0; c < 8; c++) { x[c] = src[(size_t)r*256 + lane + 32*c]; s += x[c]; }
            #pragma unroll
            for (int o = 16; o; o >>= 1) s += __shfl_xor_sync(~0u, s, o);
            float mean = s * (1.f/256.f);
            float vs = 0.f;
            #pragma unroll
            for (int c = 0; c < 8; c++) { float d = x[c] - mean; vs += d*d; }
            #pragma unroll
            for (int o = 16; o; o >>= 1) vs += __shfl_xor_sync(~0u, vs, o);
            float inv = rsqrtf(vs * (1.f/256.f) + 1e-5f);
            #pragma unroll
            for (int c = 0; c < 8; c++) {
                int col = lane + 32*c;
                float y = (x[c]-mean)*inv*gam[col] + bet[col];
                __nv_bfloat16 h, l; bsplit(y, h, l);
                Ah[r*AST + col] = h; Al[r*AST + col] = l;
            }
        } else {
            #pragma unroll
            for (int c = 0; c < 8; c++) {
                int col = lane + 32*c;
                Ah[r*AST + col] = __float2bfloat16(0.f);
                Al[r*AST + col] = __float2bfloat16(0.f);
            }
        }
    }
    __syncthreads();
}

__device__ __forceinline__ void copy_to_Abf(const float* __restrict__ src,
    __nv_bfloat16* Ah, int w, int lane)
{
    __nv_bfloat16* Al = Ah + A_LO;
    __syncthreads();
    #pragma unroll
    for (int i = 0; i < 3; i++) {
        int r = w + 8*i;
        #pragma unroll
        for (int c = 0; c < 8; c++) {
            int col = lane + 32*c;
            float y = (r < S) ? src[(size_t)r*256 + col] : 0.f;
            __nv_bfloat16 h, l; bsplit(y, h, l);
            Ah[r*AST + col] = h; Al[r*AST + col] = l;
        }
    }
    __syncthreads();
}

// ---- stream one 32-k weight chunk (hi+lo) ----
template<int NG>
__device__ __forceinline__ void issue_w(const __nv_bfloat16* __restrict__ Wh_g,
    const __nv_bfloat16* __restrict__ Wl_g, const int* colb, int kt,
    unsigned wbase, int buf, int tid)
{
    const int half = 128*NG;
    #pragma unroll
    for (int l = 0; l < NG; l++) {
        int e = tid + l*256;
        int arr = (e < half) ? 0 : 1;
        int x = (e < half) ? e : e - half;
        int n = x >> 2, q = x & 3;
        int g = n >> 5, rn = n & 31;
        const __nv_bfloat16* src =
            (arr ? Wl_g : Wh_g) + (size_t)(colb[g] + rn)*256 + kt + q*8;
        cp16(wbase + (unsigned)(buf*7680 + arr*3840 + n*WST + q*8)*2, src);
    }
    CP_COMMIT();
}

// ---- stream one 24-row x 64-k chunk of split k (for dots) ----
__device__ __forceinline__ void issue_k24(int b, int f, int jbase, int kt,
    unsigned wbase, int buf, int tid)
{
    #pragma unroll
    for (int l = 0; l < 2; l++) {
        int e = tid + l*256;
        if (e < 384) {
            int arr = (e >= 192) ? 1 : 0;
            int x = e - arr*192;
            int n = x >> 3, q = x & 7;
            const __nv_bfloat16* src =
                (arr ? g_kl : g_kh) + ((size_t)(b*NF + f)*HW + jbase + n)*256 + kt + q*8;
            cp16(wbase + (unsigned)(buf*7680 + arr*1728 + n*72 + q*8)*2, src);
        }
    }
    CP_COMMIT();
}

// ---- stream this rank's v_t tile: 32 cols x 192 j, hi+lo ----
__device__ __forceinline__ void issue_vt(int b, int f, int colq, unsigned vtbase, int tid)
{
    #pragma unroll
    for (int l = 0; l < 6; l++) {
        int e = tid + l*256;
        int arr = (e >= 768) ? 1 : 0;
        int x = e - arr*768;
        int n = x / 24, q = x % 24;
        const __nv_bfloat16* src =
            (arr ? g_vtl : g_vth) + (size_t)(b*NF + f)*(256*HW) + (size_t)(colq + n)*HW + q*8;
        cp16(vtbase + (unsigned)(arr*6400 + n*200 + q*8)*2, src);
    }
    CP_COMMIT();
}

// ---- D[24 x 32*NG] = A @ Wslice^T via bf16x3 mma; result -> sOut ----
template<int NG>
__device__ __forceinline__ void small_gemm_bf(const __nv_bfloat16* __restrict__ Wh_g,
    const __nv_bfloat16* __restrict__ Wl_g, const int* colb,
    const __nv_bfloat16* Ah, __nv_bfloat16* Wsm, unsigned wbase, float* sOut,
    int tid, int w, int lane)
{
    const __nv_bfloat16* Al = Ah + A_LO;
    float acc[NG][4];
    #pragma unroll
    for (int g = 0; g < NG; g++)
        #pragma unroll
        for (int j = 0; j < 4; j++) acc[g][j] = 0.f;

    int mt  = w >> 2;
    int ntb = (w & 3) * NG;
    int r = lane >> 2, c = lane & 3;
    int arow = mt*16 + r;

    issue_w<NG>(Wh_g, Wl_g, colb, 0, wbase, 0, tid);
    #pragma unroll
    for (int c8 = 0; c8 < 8; c8++) {
        if (c8 < 7) {
            issue_w<NG>(Wh_g, Wl_g, colb, (c8+1)*32, wbase, (c8+1)&1, tid);
            CP_WAIT1();
        } else {
            CP_WAIT0();
        }
        __syncthreads();
        const __nv_bfloat16* Wh_s = Wsm + (c8&1)*7680;
        const __nv_bfloat16* Wl_s = Wh_s + 3840;
        #pragma unroll
        for (int ks = 0; ks < 2; ks++) {
            int k0 = c8*32 + ks*16, kw = ks*16;
            unsigned ah[4], al[4];
            const __nv_bfloat16* p = Ah + arow*AST + k0 + 2*c;
            ah[0] = *(const unsigned*)p;
            ah[1] = *(const unsigned*)(p + 8*AST);
            ah[2] = *(const unsigned*)(p + 8);
            ah[3] = *(const unsigned*)(p + 8*AST + 8);
            const __nv_bfloat16* q = Al + arow*AST + k0 + 2*c;
            al[0] = *(const unsigned*)q;
            al[1] = *(const unsigned*)(q + 8*AST);
            al[2] = *(const unsigned*)(q + 8);
            al[3] = *(const unsigned*)(q + 8*AST + 8);
            #pragma unroll
            for (int g = 0; g < NG; g++) {
                int n = (ntb + g)*8 + r;
                const __nv_bfloat16* ph = Wh_s + n*WST + kw + 2*c;
                unsigned bh[2] = { *(const unsigned*)ph, *(const unsigned*)(ph + 8) };
                const __nv_bfloat16* pl = Wl_s + n*WST + kw + 2*c;
                unsigned bl[2] = { *(const unsigned*)pl, *(const unsigned*)(pl + 8) };
                mma_bf16(acc[g], ah, bh);
                mma_bf16(acc[g], ah, bl);
                mma_bf16(acc[g], al, bh);
            }
        }
        __syncthreads();
    }
    #pragma unroll
    for (int g = 0; g < NG; g++) {
        int row0 = mt*16 + r;
        int cc = (ntb + g)*8 + 2*c;
        sOut[row0*OST + cc]     = acc[g][0];
        sOut[row0*OST + cc + 1] = acc[g][1];
        if (mt == 0) {
            sOut[(row0+8)*OST + cc]     = acc[g][2];
            sOut[(row0+8)*OST + cc + 1] = acc[g][3];
        }
    }
    __syncthreads();
}

__global__ void __cluster_dims__(RANKS, 1, 1) __launch_bounds__(256, 2)
slot_loop(
    const float* __restrict__ noise, const float* __restrict__ mu,
    const float* __restrict__ sg,
    const float* __restrict__ bq,  const float* __restrict__ b1,
    const float* __restrict__ b2,
    const float* __restrict__ bih, const float* __restrict__ bhh,
    const float* __restrict__ gsl, const float* __restrict__ besl,
    const float* __restrict__ gff, const float* __restrict__ beff,
    float* __restrict__ out, float* __restrict__ out_attn)
{
    extern __shared__ char sm[];
    __nv_bfloat16* Ah  = (__nv_bfloat16*)sm;
    __nv_bfloat16* Wsm = (__nv_bfloat16*)(sm + WOFF);
    float* sOut = (float*)(sm + DOFF);
    float* sDot = (float*)(sm + DOFF);
    float* sAtt = (float*)(sm + DOFF);
    unsigned wbase  = (unsigned)__cvta_generic_to_shared(sm + WOFF);
    unsigned vtbase = (unsigned)__cvta_generic_to_shared(sm + VOFF);

    int tid  = threadIdx.x;
    int w    = tid >> 5, lane = tid & 31;
    int rank = blockIdx.x;
    int b    = blockIdx.y;
    int colq = 32*rank;
    int jbase = 24*rank;
    int col  = colq + lane;
    int mt = w >> 2, nq = w & 3;
    int fr = lane >> 2, fc = lane & 3;
    int colb1[1] = { colq };
    int colb3[3] = { colq, 256 + colq, 512 + colq };

    float* slots_b = g_slots + (size_t)b*S*256;
    float* q_b     = g_q     + (size_t)b*S*256;
    float* upd_b   = g_upd   + (size_t)b*S*256;
    float* h_b     = g_h     + (size_t)b*S*256;
    float* t_b     = g_t     + (size_t)b*S*256;
    float* attn_b  = g_attn  + (size_t)b*S*HW;

    #pragma unroll
    for (int i = 0; i < 3; i++) {
        int r = w + 8*i;
        if (r < S)
            slots_b[(size_t)r*256 + col] = mu[col] + sg[col]*noise[(size_t)(b*S + r)*256 + col];
    }
    CLUSTER_SYNC();

    float gh[3][3];
    float hreg[3];

    for (int f = 0; f < NF; f++) {
        for (int it = 0; it < 3; it++) {
            // ---- S1: q = LN_sl(slots) @ Wq^T + bq ; prefetch k chunk0 ----
            ln_to_Abf(slots_b, gsl, besl, Ah, w, lane);
            small_gemm_bf<1>(g_Wqh, g_Wql, colb1, Ah, Wsm, wbase, sOut, tid, w, lane);
            #pragma unroll
            for (int i = 0; i < 3; i++) {
                int r = w + 8*i;
                if (r < S) q_b[(size_t)r*256 + col] = sOut[r*OST + lane] + bq[col];
            }
            __syncthreads();
            issue_k24(b, f, jbase, 0, wbase, 0, tid);
            CLUSTER_SYNC();

            // ---- S2: dots via mma + softmax ; prefetch v_t ; gh GEMM ----
            copy_to_Abf(q_b, Ah, w, lane);
            {
                float dacc[4] = {0.f, 0.f, 0.f, 0.f};
                int arow = mt*16 + fr;
                #pragma unroll
                for (int ch = 0; ch < 4; ch++) {
                    if (ch < 3) {
                        issue_k24(b, f, jbase, (ch+1)*64, wbase, (ch+1)&1, tid);
                        CP_WAIT1();
                    } else {
                        CP_WAIT0();
                    }
                    __syncthreads();
                    const __nv_bfloat16* Kh = Wsm + (ch&1)*7680;
                    const __nv_bfloat16* Kl = Kh + 1728;
                    #pragma unroll
                    for (int k16 = 0; k16 < 4; k16++) {
                        int k0 = ch*64 + k16*16, kw = k16*16;
                        unsigned ah[4], al[4];
                        const __nv_bfloat16* p = Ah + arow*AST + k0 + 2*fc;
                        ah[0] = *(const unsigned*)p;
                        ah[1] = *(const unsigned*)(p + 8*AST);
                        ah[2] = *(const unsigned*)(p + 8);
                        ah[3] = *(const unsigned*)(p + 8*AST + 8);
                        const __nv_bfloat16* qp = Ah + A_LO + arow*AST + k0 + 2*fc;
                        al[0] = *(const unsigned*)qp;
                        al[1] = *(const unsigned*)(qp + 8*AST);
                        al[2] = *(const unsigned*)(qp + 8);
                        al[3] = *(const unsigned*)(qp + 8*AST + 8);
                        if (nq < 3) {
                            int n = nq*8 + fr;
                            const __nv_bfloat16* ph = Kh + n*72 + kw + 2*fc;
                            unsigned bh[2] = { *(const unsigned*)ph, *(const unsigned*)(ph + 8) };
                            const __nv_bfloat16* pl = Kl + n*72 + kw + 2*fc;
                            unsigned bl[2] = { *(const unsigned*)pl, *(const unsigned*)(pl + 8) };
                            mma_bf16(dacc, ah, bh);
                            mma_bf16(dacc, ah, bl);
                            mma_bf16(dacc, al, bh);
                        }
                    }
                    if (ch < 3) __syncthreads();
                }
                __syncthreads();
                if (nq < 3) {
                    int cc = nq*8 + 2*fc;
                    int r0 = mt*16 + fr;
                    sDot[r0*25 + cc]     = dacc[0];
                    sDot[r0*25 + cc + 1] = dacc[1];
                    if (mt == 0) {
                        sDot[(fr+8)*25 + cc]     = dacc[2];
                        sDot[(fr+8)*25 + cc + 1] = dacc[3];
                    }
                }
                __syncthreads();
            }
            issue_vt(b, f, colq, vtbase, tid);
            // softmax over slot axis: warp w owns 3 j's
            #pragma unroll
            for (int jj = 0; jj < 3; jj++) {
                int j = w*3 + jj;
                float x = (lane < S) ? sDot[lane*25 + j]*0.0625f : -1e30f;
                float mx = x;
                #pragma unroll
                for (int o = 16; o; o >>= 1) mx = fmaxf(mx, __shfl_xor_sync(~0u, mx, o));
                float e = (lane < S) ? expf(x - mx) : 0.f;
                float sum = e;
                #pragma unroll
                for (int o = 16; o; o >>= 1) sum += __shfl_xor_sync(~0u, sum, o);
                float a = e / sum + 1e-8f;
                if (lane < S) {
                    attn_b[(size_t)lane*HW + jbase + j] = a;
                    if (it == 2)
                        out_attn[(size_t)((b*NF + f)*S + lane)*HW + jbase + j] = a;
                }
            }
            // gh = slots @ Whh^T at gate cols
            copy_to_Abf(slots_b, Ah, w, lane);
            small_gemm_bf<3>(g_Whhh, g_Whhl, colb3, Ah, Wsm, wbase, sOut, tid, w, lane);
            #pragma unroll
            for (int i = 0; i < 3; i++) {
                int r = w + 8*i;
                #pragma unroll
                for (int g = 0; g < 3; g++)
                    gh[i][g] = (r < S) ? sOut[r*OST + g*32 + lane] : 0.f;
            }
            CLUSTER_SYNC();

            // ---- S3: updates = (attn/rowsum) @ v via mma ----
            __syncthreads();
            for (int l = 0; l < 16; l++) {
                int e = tid + l*256;
                if (e < S*HW) sAtt[e] = attn_b[e];
            }
            __syncthreads();
            {
                float rsv[3];
                #pragma unroll
                for (int i = 0; i < 3; i++) {
                    int r = w + 8*i;
                    if (r < S) {
                        float s = 0.f;
                        #pragma unroll
                        for (int c = 0; c < 6; c++) s += sAtt[r*HW + lane + 32*c];
                        #pragma unroll
                        for (int o = 16; o; o >>= 1) s += __shfl_xor_sync(~0u, s, o);
                        rsv[i] = 1.f / s;
                    }
                }
                // split attn/rowsum into A (cols 0..191)
                __nv_bfloat16* Alp = Ah + A_LO;
                #pragma unroll
                for (int i = 0; i < 3; i++) {
                    int r = w + 8*i;
                    #pragma unroll
                    for (int c = 0; c < 6; c++) {
                        int cc = lane + 32*c;
                        float a = (r < S) ? sAtt[r*HW + cc]*rsv[i] : 0.f;
                        __nv_bfloat16 h, l; bsplit(a, h, l);
                        Ah[r*AST + cc] = h; Alp[r*AST + cc] = l;
                    }
                }
                __syncthreads();
                float ua[4] = {0.f, 0.f, 0.f, 0.f};
                const __nv_bfloat16* Vh = (const __nv_bfloat16*)(sm + VOFF);
                const __nv_bfloat16* Vl = Vh + 6400;
                int arow = mt*16 + fr;
                int n = nq*8 + fr;
                #pragma unroll
                for (int k16 = 0; k16 < 12; k16++) {
                    int k0 = k16*16;
                    unsigned ah[4], al[4];
                    const __nv_bfloat16* p = Ah + arow*AST + k0 + 2*fc;
                    ah[0] = *(const unsigned*)p;
                    ah[1] = *(const unsigned*)(p + 8*AST);
                    ah[2] = *(const unsigned*)(p + 8);
                    ah[3] = *(const unsigned*)(p + 8*AST + 8);
                    const __nv_bfloat16* qp = Alp + arow*AST + k0 + 2*fc;
                    al[0] = *(const unsigned*)qp;
                    al[1] = *(const unsigned*)(qp + 8*AST);
                    al[2] = *(const unsigned*)(qp + 8);
                    al[3] = *(const unsigned*)(qp + 8*AST + 8);
                    const __nv_bfloat16* ph = Vh + n*200 + k0 + 2*fc;
                    unsigned bh[2] = { *(const unsigned*)ph, *(const unsigned*)(ph + 8) };
                    const __nv_bfloat16* pl = Vl + n*200 + k0 + 2*fc;
                    unsigned bl[2] = { *(const unsigned*)pl, *(const unsigned*)(pl + 8) };
                    mma_bf16(ua, ah, bh);
                    mma_bf16(ua, ah, bl);
                    mma_bf16(ua, al, bh);
                }
                int cg = colq + nq*8 + 2*fc;
                int r0 = mt*16 + fr;
                if (mt == 0) {
                    upd_b[(size_t)r0*256 + cg]       = ua[0];
                    upd_b[(size_t)r0*256 + cg + 1]   = ua[1];
                    upd_b[(size_t)(r0+8)*256 + cg]   = ua[2];
                    upd_b[(size_t)(r0+8)*256 + cg+1] = ua[3];
                } else if (r0 < S) {
                    upd_b[(size_t)r0*256 + cg]     = ua[0];
                    upd_b[(size_t)r0*256 + cg + 1] = ua[1];
                }
            }
            CLUSTER_SYNC();

            // ---- S4: gi GEMM + GRU -> h ----
            copy_to_Abf(upd_b, Ah, w, lane);
            small_gemm_bf<3>(g_Wihh, g_Wihl, colb3, Ah, Wsm, wbase, sOut, tid, w, lane);
            #pragma unroll
            for (int i = 0; i < 3; i++) {
                int r = w + 8*i;
                if (r < S) {
                    float irv = sOut[r*OST + lane]      + bih[col];
                    float izv = sOut[r*OST + 32 + lane] + bih[256 + col];
                    float inv = sOut[r*OST + 64 + lane] + bih[512 + col];
                    float hrv = gh[i][0] + bhh[col];
                    float hzv = gh[i][1] + bhh[256 + col];
                    float hnv = gh[i][2] + bhh[512 + col];
                    float rr = 1.f / (1.f + expf(-(irv + hrv)));
                    float zz = 1.f / (1.f + expf(-(izv + hzv)));
                    float nn = tanhf(inv + rr*hnv);
                    float sl = slots_b[(size_t)r*256 + col];
                    float hv = (1.f - zz)*nn + zz*sl;
                    hreg[i] = hv;
                    h_b[(size_t)r*256 + col] = hv;
                }
            }
            CLUSTER_SYNC();

            // ---- S5: t = relu(LN_ff(h) @ W1^T + b1) ----
            ln_to_Abf(h_b, gff, beff, Ah, w, lane);
            small_gemm_bf<1>(g_W1h, g_W1l, colb1, Ah, Wsm, wbase, sOut, tid, w, lane);
            #pragma unroll
            for (int i = 0; i < 3; i++) {
                int r = w + 8*i;
                if (r < S) t_b[(size_t)r*256 + col] = fmaxf(sOut[r*OST + lane] + b1[col], 0.f);
            }
            CLUSTER_SYNC();

            // ---- S6: slots = t @ W2^T + b2 + h ----
            copy_to_Abf(t_b, Ah, w, lane);
            small_gemm_bf<1>(g_W2h, g_W2l, colb1, Ah, Wsm, wbase, sOut, tid, w, lane);
            #pragma unroll
            for (int i = 0; i < 3; i++) {
                int r = w + 8*i;
                if (r < S) slots_b[(size_t)r*256 + col] = sOut[r*OST + lane] + b2[col] + hreg[i];
            }
            CLUSTER_SYNC();
        }
    }

    #pragma unroll
    for (int i = 0; i < 3; i++) {
        int r = w + 8*i;
        if (r < NA)
            out[(size_t)(b*NA + r)*256 + col] = slots_b[(size_t)r*256 + col];
    }
}

// ---------------- prepass: fused k+v GEMM; k split, v transposed+split ------
#define KVA 5120
#define KVB 20480
__global__ void __launch_bounds__(256) kv_gemm(
    const float* __restrict__ bk, const float* __restrict__ bv)
{
    extern __shared__ __nv_bfloat16 smkv[];
    unsigned sbase = (unsigned)__cvta_generic_to_shared(smkv);
    int m0 = blockIdx.y * 128;
    int which = blockIdx.x >> 1;
    int n0 = (blockIdx.x & 1) * 128;
    const __nv_bfloat16* Wh_g = which ? g_Wvh : g_Wkh;
    const __nv_bfloat16* Wl_g = which ? g_Wvl : g_Wkl;
    const float* bias = which ? bv : bk;

    int tid = threadIdx.x;
    int w = tid >> 5, lane = tid & 31;
    int wm = w >> 1, wn = w & 1;
    int r = lane >> 2, c = lane & 3;

    float acc[2][8][4];
    #pragma unroll
    for (int mt = 0; mt < 2; mt++)
        #pragma unroll
        for (int nt = 0; nt < 8; nt++)
            #pragma unroll
            for (int j = 0; j < 4; j++) acc[mt][nt][j] = 0.f;

    auto issue = [&](int kt, int buf) {
        #pragma unroll
        for (int l = 0; l < 8; l++) {
            int e = tid + l*256;
            int arr = e >> 9, x = e & 511;
            int row = x >> 2, q = x & 3;
            const __nv_bfloat16* src;
            switch (arr) {
                case 0: src = g_Ah + (size_t)(m0 + row)*256 + kt + q*8; break;
                case 1: src = g_Al + (size_t)(m0 + row)*256 + kt + q*8; break;
                case 2: src = Wh_g + (size_t)(n0 + row)*256 + kt + q*8; break;
                default:src = Wl_g + (size_t)(n0 + row)*256 + kt + q*8; break;
            }
            cp16(sbase + (unsigned)(buf*KVB + arr*KVA + row*40 + q*8)*2, src);
        }
        CP_COMMIT();
    };

    issue(0, 0);
    #pragma unroll
    for (int c8 = 0; c8 < 8; c8++) {
        if (c8 < 7) { issue((c8+1)*32, (c8+1)&1); CP_WAIT1(); }
        else        { CP_WAIT0(); }
        __syncthreads();
        const __nv_bfloat16* sAh = smkv + (c8&1)*KVB;
        const __nv_bfloat16* sAl = sAh + KVA;
        const __nv_bfloat16* sWh = sAh + 2*KVA;
        const __nv_bfloat16* sWl = sAh + 3*KVA;
        #pragma unroll
        for (int ks = 0; ks < 2; ks++) {
            int k0 = ks*16;
            unsigned ah[2][4], al[2][4];
            #pragma unroll
            for (int mt = 0; mt < 2; mt++) {
                int row = wm*32 + mt*16 + r;
                const __nv_bfloat16* p = sAh + row*40 + k0 + 2*c;
                ah[mt][0] = *(const unsigned*)p;
                ah[mt][1] = *(const unsigned*)(p + 8*40);
                ah[mt][2] = *(const unsigned*)(p + 8);
                ah[mt][3] = *(const unsigned*)(p + 8*40 + 8);
                const __nv_bfloat16* q = sAl + row*40 + k0 + 2*c;
                al[mt][0] = *(const unsigned*)q;
                al[mt][1] = *(const unsigned*)(q + 8*40);
                al[mt][2] = *(const unsigned*)(q + 8);
                al[mt][3] = *(const unsigned*)(q + 8*40 + 8);
            }
            #pragma unroll
            for (int nt = 0; nt < 8; nt++) {
                int n = wn*64 + nt*8 + r;
                const __nv_bfloat16* ph = sWh + n*40 + k0 + 2*c;
                unsigned bh[2] = { *(const unsigned*)ph, *(const unsigned*)(ph + 8) };
                const __nv_bfloat16* pl = sWl + n*40 + k0 + 2*c;
                unsigned bl[2] = { *(const unsigned*)pl, *(const unsigned*)(pl + 8) };
                #pragma unroll
                for (int mt = 0; mt < 2; mt++) {
                    mma_bf16(acc[mt][nt], ah[mt], bh);
                    mma_bf16(acc[mt][nt], ah[mt], bl);
                    mma_bf16(acc[mt][nt], al[mt], bh);
                }
            }
        }
        __syncthreads();
    }
    #pragma unroll
    for (int mt = 0; mt < 2; mt++)
        #pragma unroll
        for (int nt = 0; nt < 8; nt++) {
            int rw = m0 + wm*32 + mt*16 + r;
            int cc = n0 + wn*64 + nt*8 + 2*c;
            float v0 = acc[mt][nt][0] + bias[cc];
            float v1 = acc[mt][nt][1] + bias[cc+1];
            float v2 = acc[mt][nt][2] + bias[cc];
            float v3 = acc[mt][nt][3] + bias[cc+1];
            if (which == 0) {
                __nv_bfloat16 h, l;
                bsplit(v0, h, l); g_kh[(size_t)rw*256 + cc]     = h; g_kl[(size_t)rw*256 + cc]     = l;
                bsplit(v1, h, l); g_kh[(size_t)rw*256 + cc + 1] = h; g_kl[(size_t)rw*256 + cc + 1] = l;
                bsplit(v2, h, l); g_kh[(size_t)(rw+8)*256 + cc]     = h; g_kl[(size_t)(rw+8)*256 + cc]     = l;
                bsplit(v3, h, l); g_kh[(size_t)(rw+8)*256 + cc + 1] = h; g_kl[(size_t)(rw+8)*256 + cc + 1] = l;
            } else {
                __nv_bfloat16 h, l;
                int bf0 = rw / HW, j0 = rw - bf0*HW;
                int bf1 = (rw+8) / HW, j1 = (rw+8) - bf1*HW;
                size_t i00 = (size_t)bf0*(256*HW) + (size_t)cc*HW + j0;
                size_t i01 = i00 + HW;
                size_t i10 = (size_t)bf1*(256*HW) + (size_t)cc*HW + j1;
                size_t i11 = i10 + HW;
                bsplit(v0, h, l); g_vth[i00] = h; g_vtl[i00] = l;
                bsplit(v1, h, l); g_vth[i01] = h; g_vtl[i01] = l;
                bsplit(v2, h, l); g_vth[i10] = h; g_vtl[i10] = l;
                bsplit(v3, h, l); g_vth[i11] = h; g_vtl[i11] = l;
            }
        }
}

__global__ void __launch_bounds__(256) ln_kernel(const float* __restrict__ X,
    const float* __restrict__ g, const float* __restrict__ be)
{
    int w = threadIdx.x >> 5, lane = threadIdx.x & 31;
    size_t row = (size_t)blockIdx.x*8 + w;
    const float* Xr = X + row*256;
    float x[8]; float s = 0.f;
    #pragma unroll
    for (int c = 0; c < 8; c++) { x[c] = Xr[lane + 32*c]; s += x[c]; }
    #pragma unroll
    for (int o = 16; o; o >>= 1) s += __shfl_xor_sync(~0u, s, o);
    float mean = s * (1.f/256.f);
    float vs = 0.f;
    #pragma unroll
    for (int c = 0; c < 8; c++) { float d = x[c] - mean; vs += d*d; }
    #pragma unroll
    for (int o = 16; o; o >>= 1) vs += __shfl_xor_sync(~0u, vs, o);
    float inv = rsqrtf(vs * (1.f/256.f) + 1e-5f);
    #pragma unroll
    for (int c = 0; c < 8; c++) {
        int col = lane + 32*c;
        float y = (x[c]-mean)*inv*g[col] + be[col];
        __nv_bfloat16 h, l; bsplit(y, h, l);
        g_Ah[row*256 + col] = h;
        g_Al[row*256 + col] = l;
    }
}

__global__ void conv_split(const float* __restrict__ W,
    __nv_bfloat16* __restrict__ Hp, __nv_bfloat16* __restrict__ Lp, int n)
{
    int i = blockIdx.x*256 + threadIdx.x;
    if (i < n) {
        __nv_bfloat16 h, l; bsplit(W[i], h, l);
        Hp[i] = h; Lp[i] = l;
    }
}

extern "C" void kernel_launch(void* const* d_in, const int* in_sizes, int n_in,
                              void* d_out, int out_size)
{
    const float* inputs = (const float*)d_in[0];
    const float* noise  = (const float*)d_in[1];
    const float* mu     = (const float*)d_in[2];
    const float* sigma  = (const float*)d_in[3];
    const float* Wq  = (const float*)d_in[4];  const float* bq  = (const float*)d_in[5];
    const float* Wk  = (const float*)d_in[6];  const float* bk  = (const float*)d_in[7];
    const float* Wv  = (const float*)d_in[8];  const float* bv  = (const float*)d_in[9];
    const float* W1  = (const float*)d_in[10]; const float* b1  = (const float*)d_in[11];
    const float* W2  = (const float*)d_in[12]; const float* b2  = (const float*)d_in[13];
    const float* Wih = (const float*)d_in[14]; const float* bih = (const float*)d_in[15];
    const float* Whh = (const float*)d_in[16]; const float* bhh = (const float*)d_in[17];
    const float* gin = (const float*)d_in[18]; const float* bein = (const float*)d_in[19];
    const float* gsl = (const float*)d_in[20]; const float* besl = (const float*)d_in[21];
    const float* gff = (const float*)d_in[22]; const float* beff = (const float*)d_in[23];

    float* out = (float*)d_out;
    float* out_attn = out + (size_t)B*NA*D;

    __nv_bfloat16 *wkh,*wkl,*wvh,*wvl,*wqh,*wql,*w1h,*w1l,*w2h,*w2l,*wihh,*wihl,*whhh,*whhl;
    cudaGetSymbolAddress((void**)&wkh, g_Wkh);  cudaGetSymbolAddress((void**)&wkl, g_Wkl);
    cudaGetSymbolAddress((void**)&wvh, g_Wvh);  cudaGetSymbolAddress((void**)&wvl, g_Wvl);
    cudaGetSymbolAddress((void**)&wqh, g_Wqh);  cudaGetSymbolAddress((void**)&wql, g_Wql);
    cudaGetSymbolAddress((void**)&w1h, g_W1h);  cudaGetSymbolAddress((void**)&w1l, g_W1l);
    cudaGetSymbolAddress((void**)&w2h, g_W2h);  cudaGetSymbolAddress((void**)&w2l, g_W2l);
    cudaGetSymbolAddress((void**)&wihh, g_Wihh); cudaGetSymbolAddress((void**)&wihl, g_Wihl);
    cudaGetSymbolAddress((void**)&whhh, g_Whhh); cudaGetSymbolAddress((void**)&whhl, g_Whhl);

    cudaFuncSetAttribute(slot_loop, cudaFuncAttributeMaxDynamicSharedMemorySize, LOOP_SMEM);
    cudaFuncSetAttribute(kv_gemm,   cudaFuncAttributeMaxDynamicSharedMemorySize, 2*KVB*2);

    conv_split<<<256, 256>>>(Wk,  wkh,  wkl,  D*D);
    conv_split<<<256, 256>>>(Wv,  wvh,  wvl,  D*D);
    conv_split<<<256, 256>>>(Wq,  wqh,  wql,  D*D);
    conv_split<<<256, 256>>>(W1,  w1h,  w1l,  D*D);
    conv_split<<<256, 256>>>(W2,  w2h,  w2l,  D*D);
    conv_split<<<768, 256>>>(Wih, wihh, wihl, 3*D*D);
    conv_split<<<768, 256>>>(Whh, whhh, whhl, 3*D*D);

    ln_kernel<<<RTOT/8, 256>>>(inputs, gin, bein);
    kv_gemm<<<dim3(4, RTOT/128), 256, 2*KVB*2>>>(bk, bv);

    slot_loop<<<dim3(RANKS, B), 256, LOOP_SMEM>>>(
        noise, mu, sigma, bq, b1, b2, bih, bhh,
        gsl, besl, gff, beff, out, out_attn);
}